// round 16
// baseline (speedup 1.0000x reference)
#include <cuda_runtime.h>
#include <math.h>

#define BB 128
#define SS 512
#define EE 256
#define HH 256
#define G4 1024
#define NT 20
#define M_TOT (BB*SS)          // 65536
#define NBLK 64                // blocks per direction in lstm kernel
#define DPB 4                  // hidden dims per block

typedef unsigned long long ull;

// -------- device scratch (static: no allocations allowed) --------
// g_xp layout: [dir][t][gate_row 1024][b 128]  (536 MB)
__device__ float g_xp[2 * SS * G4 * BB];
__device__ float g_hout[2 * M_TOT * HH];   // [dir][b*S+t][H]
__device__ float g_hcur[2 * 2 * HH * BB];  // [dir][parity][hd][b]
__device__ float g_emis[M_TOT * NT];       // [b*S+s][T]
__device__ unsigned g_bar_cnt[2];
__device__ unsigned g_bar_flag[2];

// smem floats: h 256*128 + w 256*16 + pg 2*16*128 + x 16*128 + c 4*128
#define LSTM_SMEM ((256*128 + 256*16 + 2*16*128 + 16*128 + 4*128) * 4)

// -------- packed f32x2 helpers (FFMA2 path, exact fp32) --------
__device__ __forceinline__ void upk2(ull v, float& lo, float& hi) {
    asm("mov.b64 {%0, %1}, %2;" : "=f"(lo), "=f"(hi) : "l"(v));
}
__device__ __forceinline__ ull dup2(float x) {
    ull r; asm("mov.b64 %0, {%1, %1};" : "=l"(r) : "f"(x)); return r;
}
__device__ __forceinline__ void fma2(ull& d, ull a, ull b) {
    asm("fma.rn.f32x2 %0, %1, %2, %0;" : "+l"(d) : "l"(a), "l"(b));
}
__device__ __forceinline__ void cp16(unsigned dst, const void* src) {
    asm volatile("cp.async.cg.shared.global [%0], [%1], 16;" :: "r"(dst), "l"(src));
}
#define CP_COMMIT() asm volatile("cp.async.commit_group;")

// ---------------- init: reset barriers + zero h state ----------------
__global__ void init_kernel() {
    int idx = blockIdx.x * blockDim.x + threadIdx.x;
    int stride = gridDim.x * blockDim.x;
    for (int i = idx; i < 2 * 2 * HH * BB; i += stride) g_hcur[i] = 0.f;
    if (idx == 0) {
        g_bar_cnt[0] = 0; g_bar_cnt[1] = 0;
        g_bar_flag[0] = 0; g_bar_flag[1] = 0;
    }
}

// ---------------- input projection: xp = emb[xs] @ W_ih^T + b ----------------
// 128x128 tile (all 128 batches at fixed t x 128 gate rows), K panels of 16,
// 256 threads, 8x8 per thread via FFMA2 (row-pairs packed, cols reg-duplicated).
// Output TRANSPOSED: g_xp[dir][t][n][b].
__global__ void __launch_bounds__(256, 1)
input_proj_kernel(const int* __restrict__ xs,
                  const float* __restrict__ emb,
                  const float* __restrict__ W_f,
                  const float* __restrict__ b_f,
                  const float* __restrict__ W_r,
                  const float* __restrict__ b_r)
{
    const int dir = blockIdx.z;
    const float* W    = dir ? W_r : W_f;
    const float* bias = dir ? b_r : b_f;
    const int t  = blockIdx.x;
    const int n0 = blockIdx.y * 128;

    __shared__ float As[16][132];   // [k][batch]
    __shared__ float Bs[16][132];   // [k][gate row]

    const int tid = threadIdx.x;
    const int lr = tid >> 1;          // 0..127
    const int lk = (tid & 1) * 8;     // 0 or 8

    const int tok = xs[lr * SS + t];
    const float* arow = emb + (size_t)tok * EE;
    const float* brow = W + (size_t)(n0 + lr) * EE;

    const int ty = tid >> 4;          // 0..15 -> batches ty*8..+8
    const int tx = tid & 15;          // 0..15 -> cols tx*8..+8

    ull acc[4][8];                    // [row-pair][col]
    #pragma unroll
    for (int i = 0; i < 4; i++)
        #pragma unroll
        for (int j = 0; j < 8; j++) acc[i][j] = 0ull;

    float4 a0 = *(const float4*)(arow + lk);
    float4 a1 = *(const float4*)(arow + lk + 4);
    float4 bv0 = *(const float4*)(brow + lk);
    float4 bv1 = *(const float4*)(brow + lk + 4);

    #pragma unroll 1
    for (int p = 0; p < 16; p++) {
        __syncthreads();
        As[lk+0][lr] = a0.x; As[lk+1][lr] = a0.y; As[lk+2][lr] = a0.z; As[lk+3][lr] = a0.w;
        As[lk+4][lr] = a1.x; As[lk+5][lr] = a1.y; As[lk+6][lr] = a1.z; As[lk+7][lr] = a1.w;
        Bs[lk+0][lr] = bv0.x; Bs[lk+1][lr] = bv0.y; Bs[lk+2][lr] = bv0.z; Bs[lk+3][lr] = bv0.w;
        Bs[lk+4][lr] = bv1.x; Bs[lk+5][lr] = bv1.y; Bs[lk+6][lr] = bv1.z; Bs[lk+7][lr] = bv1.w;
        __syncthreads();
        if (p < 15) {
            const int ko = (p + 1) * 16 + lk;
            a0  = *(const float4*)(arow + ko);
            a1  = *(const float4*)(arow + ko + 4);
            bv0 = *(const float4*)(brow + ko);
            bv1 = *(const float4*)(brow + ko + 4);
        }
        #pragma unroll
        for (int k = 0; k < 16; k++) {
            ulonglong2 ax = *(const ulonglong2*)(&As[k][ty * 8]);      // pairs (0,1),(2,3)
            ulonglong2 ay = *(const ulonglong2*)(&As[k][ty * 8 + 4]);  // pairs (4,5),(6,7)
            float4 bb0 = *(const float4*)(&Bs[k][tx * 8]);
            float4 bb1 = *(const float4*)(&Bs[k][tx * 8 + 4]);
            ull w0 = dup2(bb0.x), w1 = dup2(bb0.y), w2 = dup2(bb0.z), w3 = dup2(bb0.w);
            ull w4 = dup2(bb1.x), w5 = dup2(bb1.y), w6 = dup2(bb1.z), w7 = dup2(bb1.w);
            fma2(acc[0][0], ax.x, w0); fma2(acc[1][0], ax.y, w0);
            fma2(acc[2][0], ay.x, w0); fma2(acc[3][0], ay.y, w0);
            fma2(acc[0][1], ax.x, w1); fma2(acc[1][1], ax.y, w1);
            fma2(acc[2][1], ay.x, w1); fma2(acc[3][1], ay.y, w1);
            fma2(acc[0][2], ax.x, w2); fma2(acc[1][2], ax.y, w2);
            fma2(acc[2][2], ay.x, w2); fma2(acc[3][2], ay.y, w2);
            fma2(acc[0][3], ax.x, w3); fma2(acc[1][3], ax.y, w3);
            fma2(acc[2][3], ay.x, w3); fma2(acc[3][3], ay.y, w3);
            fma2(acc[0][4], ax.x, w4); fma2(acc[1][4], ax.y, w4);
            fma2(acc[2][4], ay.x, w4); fma2(acc[3][4], ay.y, w4);
            fma2(acc[0][5], ax.x, w5); fma2(acc[1][5], ax.y, w5);
            fma2(acc[2][5], ay.x, w5); fma2(acc[3][5], ay.y, w5);
            fma2(acc[0][6], ax.x, w6); fma2(acc[1][6], ax.y, w6);
            fma2(acc[2][6], ay.x, w6); fma2(acc[3][6], ay.y, w6);
            fma2(acc[0][7], ax.x, w7); fma2(acc[1][7], ax.y, w7);
            fma2(acc[2][7], ay.x, w7); fma2(acc[3][7], ay.y, w7);
        }
    }

    // transposed store: g_xp[((dir*SS+t)*G4 + n)*BB + b], batches ty*8..+8
    const size_t obase = ((size_t)dir * SS + t) * G4;
    #pragma unroll
    for (int j = 0; j < 8; j++) {
        const int n = n0 + tx * 8 + j;
        const float bs = bias[n];
        float r0, r1, r2, r3, r4, r5, r6, r7;
        upk2(acc[0][j], r0, r1); upk2(acc[1][j], r2, r3);
        upk2(acc[2][j], r4, r5); upk2(acc[3][j], r6, r7);
        float4 o0, o1;
        o0.x = r0 + bs; o0.y = r1 + bs; o0.z = r2 + bs; o0.w = r3 + bs;
        o1.x = r4 + bs; o1.y = r5 + bs; o1.z = r6 + bs; o1.w = r7 + bs;
        float* dst = g_xp + (obase + n) * BB + ty * 8;
        *(float4*)dst = o0;
        *(float4*)(dst + 4) = o1;
    }
}

// ---------------- persistent bidirectional LSTM recurrence ----------------
// 128 blocks: [0,64) fwd, [64,128) rev. Block owns 4 hidden dims = 16 gate cols.
// 16 cells/thread (4b x 4c), k-split halves, FFMA2 with register-duplicated W.
__global__ void __launch_bounds__(256, 1) lstm_kernel(const float* __restrict__ W_f,
                                                      const float* __restrict__ W_r)
{
    extern __shared__ float sm[];
    float* h_s = sm;                       // [k=256][b=128]
    float* w_s = h_s + 256 * 128;          // [k=256][c=16]
    float* pg  = w_s + 256 * 16;           // [half=2][c=16][b=128]
    float* x_s = pg  + 2 * 16 * 128;       // [c=16][b=128]
    float* c_s = x_s + 16 * 128;           // [d=4][b=128]

    const int tid = threadIdx.x;
    const int dir = blockIdx.x >> 6;
    const int blk = blockIdx.x & 63;
    const int d0  = blk * DPB;
    const float* W = dir ? W_r : W_f;

    // load W slice transposed: w_s[k][c] = W[q*256+d0+dd][k], c = q*4+dd
    {
        const int c  = tid >> 4;               // 0..15
        const int q  = c >> 2, dd = c & 3;
        const int grow = q * 256 + d0 + dd;
        const int kc = (tid & 15) * 16;
        const float* wp = W + (size_t)grow * 256 + kc;
        #pragma unroll
        for (int kk = 0; kk < 16; kk++)
            w_s[(kc + kk) * 16 + c] = wp[kk];
    }
    for (int i = tid; i < DPB * BB; i += 256) c_s[i] = 0.f;
    __syncthreads();

    const int half = tid >> 7;           // k range half*128 .. +128
    const int wt   = tid & 127;
    const int bg   = wt >> 2;            // 0..31 -> batches bg*4..+3
    const int cq   = wt & 3;             // 0..3  -> cols cq*4..+3 (gate cq, dims 0..3)
    const int b0   = bg * 4;

    const float* xpT       = g_xp   + (size_t)dir * SS * G4 * BB;
    float*       hout_base = g_hout + (size_t)dir * M_TOT * HH;
    const unsigned h_addr = (unsigned)__cvta_generic_to_shared(h_s);
    const unsigned x_addr = (unsigned)__cvta_generic_to_shared(x_s);

    for (int ti = 0; ti < SS; ti++) {
        const int t = dir ? (SS - 1 - ti) : ti;
        const int par = ti & 1;
        const float* hr = g_hcur + (dir * 2 + par) * (HH * BB);
        float*       hw = g_hcur + (dir * 2 + (par ^ 1)) * (HH * BB);

        // --- staging: half0 copies h rows 0..127 + xp; half1 copies h rows 128..255
        if (half == 0) {
            const float4* src = (const float4*)hr;
            #pragma unroll
            for (int i = 0; i < 32; i++) {
                int idx = i * 128 + wt;            // 0..4095 (rows 0..127)
                cp16(h_addr + idx * 16, src + idx);
            }
            CP_COMMIT();
            const float* xt = xpT + (size_t)t * G4 * BB;
            #pragma unroll
            for (int i = 0; i < 4; i++) {
                int id = i * 128 + wt;             // 0..511 float4 units
                int c = id >> 5, bq = id & 31;
                int q = c >> 2, dd = c & 3;
                const float* s = xt + (size_t)(q * 256 + d0 + dd) * BB + bq * 4;
                cp16(x_addr + id * 16, s);
            }
            CP_COMMIT();
            asm volatile("cp.async.wait_group 1;");   // h rows 0..127 done
            asm volatile("bar.sync 1, 128;");
        } else {
            const float4* src = (const float4*)hr;
            #pragma unroll
            for (int i = 0; i < 32; i++) {
                int idx = 4096 + i * 128 + wt;     // rows 128..255
                cp16(h_addr + idx * 16, src + idx);
            }
            CP_COMMIT();
            asm volatile("cp.async.wait_group 0;");
            asm volatile("bar.sync 2, 128;");
        }

        // --- GEMM over this half's k range: 16 cells (4b x 4c), FFMA2 batch pairs
        ull a0[4], a1[4];   // a0[j] = (b0,b1) col j ; a1[j] = (b2,b3) col j
        #pragma unroll
        for (int j = 0; j < 4; j++) { a0[j] = 0ull; a1[j] = 0ull; }

        const float* hp = h_s + half * 128 * 128 + b0;
        const float* wp = w_s + half * 128 * 16 + cq * 4;
        #pragma unroll 8
        for (int k = 0; k < 128; k++) {
            ulonglong2 hv = *(const ulonglong2*)(hp + k * 128);
            float4 wv = *(const float4*)(wp + k * 16);
            ull w0 = dup2(wv.x), w1 = dup2(wv.y), w2 = dup2(wv.z), w3 = dup2(wv.w);
            fma2(a0[0], hv.x, w0); fma2(a1[0], hv.y, w0);
            fma2(a0[1], hv.x, w1); fma2(a1[1], hv.y, w1);
            fma2(a0[2], hv.x, w2); fma2(a1[2], hv.y, w2);
            fma2(a0[3], hv.x, w3); fma2(a1[3], hv.y, w3);
        }

        // write partials: pg[half][c][b]
        {
            float* pgh = pg + half * 2048;
            #pragma unroll
            for (int j = 0; j < 4; j++) {
                ulonglong2 s; s.x = a0[j]; s.y = a1[j];
                *(ulonglong2*)(pgh + (cq * 4 + j) * 128 + b0) = s;
            }
        }
        if (half == 0) asm volatile("cp.async.wait_group 0;");  // xp group done
        __syncthreads();

        // --- gate math: 512 (d,b) pairs, 2 per thread; keep hv for deferred hout store
        float hvv[2]; int dl[2], bl[2];
        #pragma unroll
        for (int r = 0; r < 2; r++) {
            const int idx = tid + r * 256;
            const int d = idx >> 7, b = idx & 127;
            const float gi = pg[(0*4+d)*128+b] + pg[2048+(0*4+d)*128+b] + x_s[(0*4+d)*128+b];
            const float gf = pg[(1*4+d)*128+b] + pg[2048+(1*4+d)*128+b] + x_s[(1*4+d)*128+b];
            const float gg = pg[(2*4+d)*128+b] + pg[2048+(2*4+d)*128+b] + x_s[(2*4+d)*128+b];
            const float go = pg[(3*4+d)*128+b] + pg[2048+(3*4+d)*128+b] + x_s[(3*4+d)*128+b];
            const float cp = c_s[d * 128 + b];
            const float si = 1.f / (1.f + expf(-gi));
            const float sf = 1.f / (1.f + expf(-gf));
            const float so = 1.f / (1.f + expf(-go));
            const float cn = sf * cp + si * tanhf(gg);
            const float hv = so * tanhf(cn);
            c_s[d * 128 + b] = cn;
            __stcg(hw + (d0 + d) * BB + b, hv);
            hvv[r] = hv; dl[r] = d; bl[r] = b;
        }

        // --- grid barrier: acq_rel arrive, hout stores overlapped with poll
        __syncthreads();   // all hw stores issued; cta-scope order feeds tid0's release
        int need_poll = 0;
        if (tid == 0) {
            const unsigned target = (unsigned)(NBLK * (ti + 1));
            unsigned a;
            asm volatile("atom.add.acq_rel.gpu.u32 %0, [%1], 1;"
                         : "=r"(a) : "l"(&g_bar_cnt[dir]) : "memory");
            if (a == target - 1) {
                asm volatile("st.release.gpu.u32 [%0], %1;"
                             :: "l"(&g_bar_flag[dir]), "r"((unsigned)(ti + 1)) : "memory");
            } else {
                need_poll = 1;
            }
        }
        // hout stores (read only post-kernel; no intra-kernel ordering needed)
        #pragma unroll
        for (int r = 0; r < 2; r++)
            hout_base[((size_t)bl[r] * SS + t) * HH + d0 + dl[r]] = hvv[r];
        if (need_poll) {
            unsigned f;
            do {
                asm volatile("ld.acquire.gpu.u32 %0, [%1];"
                             : "=r"(f) : "l"(&g_bar_flag[dir]) : "memory");
                if (f >= (unsigned)(ti + 1)) break;
                __nanosleep(32);
            } while (true);
        }
        __syncthreads();
    }
}

// ---------------- emissions: concat(h_f,h_r) @ fc_W^T + fc_b ----------------
__global__ void emis_kernel(const float* __restrict__ fcW, const float* __restrict__ fcb)
{
    __shared__ float w_sh[NT * 2 * HH];   // 40 KB
    __shared__ float b_sh[NT];
    const int tid = threadIdx.x;
    for (int i = tid; i < NT * 2 * HH; i += 256) w_sh[i] = fcW[i];
    if (tid < NT) b_sh[tid] = fcb[tid];
    __syncthreads();

    const int warp = tid >> 5, lane = tid & 31;
    const int pos = blockIdx.x * 8 + warp;  // 0..65535
    const float* hf = g_hout + (size_t)pos * HH;
    const float* hr = g_hout + (size_t)M_TOT * HH + (size_t)pos * HH;

    ulonglong2 Fa = *(const ulonglong2*)(hf + lane * 8);
    ulonglong2 Fb = *(const ulonglong2*)(hf + lane * 8 + 4);
    ulonglong2 Ra = *(const ulonglong2*)(hr + lane * 8);
    ulonglong2 Rb = *(const ulonglong2*)(hr + lane * 8 + 4);

    for (int tg = 0; tg < NT; tg++) {
        const float* w = w_sh + tg * 2 * HH;
        ulonglong2 Wa = *(const ulonglong2*)(w + lane * 8);
        ulonglong2 Wb = *(const ulonglong2*)(w + lane * 8 + 4);
        ulonglong2 Va = *(const ulonglong2*)(w + HH + lane * 8);
        ulonglong2 Vb = *(const ulonglong2*)(w + HH + lane * 8 + 4);
        ull acc = 0ull;
        fma2(acc, Fa.x, Wa.x); fma2(acc, Fa.y, Wa.y);
        fma2(acc, Fb.x, Wb.x); fma2(acc, Fb.y, Wb.y);
        fma2(acc, Ra.x, Va.x); fma2(acc, Ra.y, Va.y);
        fma2(acc, Rb.x, Vb.x); fma2(acc, Rb.y, Vb.y);
        float lo, hi; upk2(acc, lo, hi);
        float s = lo + hi;
        #pragma unroll
        for (int off = 16; off; off >>= 1) s += __shfl_xor_sync(0xffffffffu, s, off);
        if (lane == 0) g_emis[(size_t)pos * NT + tg] = s + b_sh[tg];
    }
}

// ---------------- Viterbi: one block (1 warp) per batch item ----------------
__global__ void viterbi_kernel(const int* __restrict__ xs,
                               const float* __restrict__ trans,
                               const float* __restrict__ start_t,
                               const float* __restrict__ end_t,
                               float* __restrict__ out,
                               int write_scores, int write_tags, int tag_off)
{
    __shared__ float tr[NT * NT];
    __shared__ float sc[NT];
    __shared__ unsigned char bp[SS * NT];

    const int b = blockIdx.x, tid = threadIdx.x;
    for (int i = tid; i < NT * NT; i += 32) tr[i] = trans[i];
    if (tid < NT) sc[tid] = start_t[tid] + g_emis[(size_t)b * SS * NT + tid];
    __syncwarp();

    for (int s = 1; s < SS; s++) {
        float ns = 0.f; int nb = 0;
        if (tid < NT) {
            float best = -1e30f; int bi = 0;
            #pragma unroll
            for (int i = 0; i < NT; i++) {
                float v = sc[i] + tr[i * NT + tid];
                if (v > best) { best = v; bi = i; }   // first-max on ties
            }
            const int m = xs[b * SS + s] > 0;
            const float em = g_emis[((size_t)b * SS + s) * NT + tid];
            ns = m ? (best + em) : sc[tid];
            nb = m ? bi : tid;
        }
        __syncwarp();
        if (tid < NT) { sc[tid] = ns; bp[s * NT + tid] = (unsigned char)nb; }
        __syncwarp();
    }

    if (tid == 0) {
        float best = -1e30f; int bi = 0;
        for (int j = 0; j < NT; j++) {
            float v = sc[j] + end_t[j];
            if (v > best) { best = v; bi = j; }
        }
        if (write_scores) out[b] = best;
        if (write_tags) {
            int tag = bi;
            out[tag_off + b * SS + (SS - 1)] = (float)tag;
            for (int s = SS - 2; s >= 0; s--) {
                tag = bp[(s + 1) * NT + tag];
                out[tag_off + b * SS + s] = (float)tag;
            }
        }
    }
}

// ---------------- launch ----------------
extern "C" void kernel_launch(void* const* d_in, const int* in_sizes, int n_in,
                              void* d_out, int out_size)
{
    const int*   xs      = (const int*)  d_in[0];
    const float* emb     = (const float*)d_in[1];
    const float* W_ih_f  = (const float*)d_in[2];
    const float* W_hh_f  = (const float*)d_in[3];
    const float* b_f     = (const float*)d_in[4];
    const float* W_ih_r  = (const float*)d_in[5];
    const float* W_hh_r  = (const float*)d_in[6];
    const float* b_r     = (const float*)d_in[7];
    const float* fc_W    = (const float*)d_in[8];
    const float* fc_b    = (const float*)d_in[9];
    const float* trans   = (const float*)d_in[10];
    const float* start_t = (const float*)d_in[11];
    const float* end_t   = (const float*)d_in[12];
    float* out = (float*)d_out;

    cudaFuncSetAttribute(lstm_kernel, cudaFuncAttributeMaxDynamicSharedMemorySize, LSTM_SMEM);

    init_kernel<<<256, 256>>>();

    // grid: x = t, y = n-tile (128 wide), z = dir
    dim3 gA(SS, G4 / 128, 2);
    input_proj_kernel<<<gA, 256>>>(xs, emb, W_ih_f, b_f, W_ih_r, b_r);

    lstm_kernel<<<2 * NBLK, 256, LSTM_SMEM>>>(W_hh_f, W_hh_r);

    emis_kernel<<<M_TOT / 8, 256>>>(fc_W, fc_b);

    int ws = 0, wt = 0, toff = 0;
    if (out_size >= BB + BB * SS)      { ws = 1; wt = 1; toff = BB; }
    else if (out_size >= BB * SS)      { ws = 0; wt = 1; toff = 0; }
    else                               { ws = 1; wt = 0; toff = 0; }
    viterbi_kernel<<<BB, 32>>>(xs, trans, start_t, end_t, out, ws, wt, toff);
}

// round 17
// speedup vs baseline: 1.0611x; 1.0611x over previous
#include <cuda_runtime.h>
#include <math.h>

#define BB 128
#define SS 512
#define EE 256
#define HH 256
#define G4 1024
#define NT 20
#define M_TOT (BB*SS)          // 65536
#define NBLK 64                // blocks per direction in lstm kernel
#define DPB 4                  // hidden dims per block

typedef unsigned long long ull;

// -------- device scratch (static: no allocations allowed) --------
// g_xp layout: [dir][t][gate_row 1024][b 128]  (536 MB)
__device__ float g_xp[2 * SS * G4 * BB];
// g_hout layout: [dir][t][d 256][b 128]  (coalesced stores from lstm)
__device__ float g_hout[2 * SS * HH * BB];
__device__ float g_hcur[2 * 2 * HH * BB];  // [dir][parity][hd][b]
__device__ float g_emis[M_TOT * NT];       // [b*S+s][T]
__device__ unsigned g_bar_cnt[2];
__device__ unsigned g_bar_flag[2];

// lstm smem floats: h 256*128 + w 256*16 + pg 2*16*128 + x 16*128 + c 4*128, + 32B mbars
#define LSTM_SMEM_FLOATS (256*128 + 256*16 + 2*16*128 + 16*128 + 4*128)
#define LSTM_SMEM (LSTM_SMEM_FLOATS * 4 + 32)

// emis smem: wT 512*20 + h 64*128 + bias 20
#define EMIS_SMEM ((512*20 + 64*128 + 32) * 4)

// -------- packed f32x2 helpers (FFMA2 path, exact fp32) --------
__device__ __forceinline__ void upk2(ull v, float& lo, float& hi) {
    asm("mov.b64 {%0, %1}, %2;" : "=f"(lo), "=f"(hi) : "l"(v));
}
__device__ __forceinline__ ull dup2(float x) {
    ull r; asm("mov.b64 %0, {%1, %1};" : "=l"(r) : "f"(x)); return r;
}
__device__ __forceinline__ void fma2(ull& d, ull a, ull b) {
    asm("fma.rn.f32x2 %0, %1, %2, %0;" : "+l"(d) : "l"(a), "l"(b));
}
__device__ __forceinline__ void cp16(unsigned dst, const void* src) {
    asm volatile("cp.async.cg.shared.global [%0], [%1], 16;" :: "r"(dst), "l"(src));
}
#define CP_COMMIT() asm volatile("cp.async.commit_group;")

// -------- TMA bulk + mbarrier helpers --------
__device__ __forceinline__ void mbar_init(unsigned mbar, unsigned cnt) {
    asm volatile("mbarrier.init.shared.b64 [%0], %1;" :: "r"(mbar), "r"(cnt) : "memory");
}
__device__ __forceinline__ void mbar_expect(unsigned mbar, unsigned tx) {
    asm volatile("mbarrier.arrive.expect_tx.shared.b64 _, [%0], %1;"
                 :: "r"(mbar), "r"(tx) : "memory");
}
__device__ __forceinline__ void bulk_g2s(unsigned dst, const void* src, unsigned bytes, unsigned mbar) {
    asm volatile("cp.async.bulk.shared::cta.global.mbarrier::complete_tx::bytes "
                 "[%0], [%1], %2, [%3];"
                 :: "r"(dst), "l"(src), "r"(bytes), "r"(mbar) : "memory");
}
__device__ __forceinline__ void mbar_wait(unsigned mbar, unsigned parity) {
    asm volatile(
        "{\n\t.reg .pred P;\n"
        "W_%=:\n\t"
        "mbarrier.try_wait.parity.shared.b64 P, [%0], %1;\n\t"
        "@!P bra W_%=;\n\t}"
        :: "r"(mbar), "r"(parity) : "memory");
}

// ---------------- init: reset barriers + zero h state ----------------
__global__ void init_kernel() {
    int idx = blockIdx.x * blockDim.x + threadIdx.x;
    int stride = gridDim.x * blockDim.x;
    for (int i = idx; i < 2 * 2 * HH * BB; i += stride) g_hcur[i] = 0.f;
    if (idx == 0) {
        g_bar_cnt[0] = 0; g_bar_cnt[1] = 0;
        g_bar_flag[0] = 0; g_bar_flag[1] = 0;
    }
}

// ---------------- input projection: xp = emb[xs] @ W_ih^T + b ----------------
// 128x128 tile (128 batches at fixed t x 128 gate rows), K panels of 16,
// 256 threads, 8x8 per thread via FFMA2 (batch-pairs packed, cols reg-duplicated).
// Thread map: tx -> batches (fast), ty -> cols, so stores of the transposed
// output g_xp[dir][t][n][b] are fully coalesced (512B per warp-row).
__global__ void __launch_bounds__(256, 1)
input_proj_kernel(const int* __restrict__ xs,
                  const float* __restrict__ emb,
                  const float* __restrict__ W_f,
                  const float* __restrict__ b_f,
                  const float* __restrict__ W_r,
                  const float* __restrict__ b_r)
{
    const int dir = blockIdx.z;
    const float* W    = dir ? W_r : W_f;
    const float* bias = dir ? b_r : b_f;
    const int t  = blockIdx.x;
    const int n0 = blockIdx.y * 128;

    __shared__ float As[16][132];   // [k][batch]
    __shared__ float Bs[16][132];   // [k][gate row]

    const int tid = threadIdx.x;
    const int lr = tid >> 1;          // 0..127
    const int lk = (tid & 1) * 8;     // 0 or 8

    const int tok = xs[lr * SS + t];
    const float* arow = emb + (size_t)tok * EE;
    const float* brow = W + (size_t)(n0 + lr) * EE;

    const int tx = tid & 15;          // 0..15 -> batches tx*8..+8
    const int ty = tid >> 4;          // 0..15 -> cols ty*8..+8

    ull acc[4][8];                    // [batch-pair][col]
    #pragma unroll
    for (int i = 0; i < 4; i++)
        #pragma unroll
        for (int j = 0; j < 8; j++) acc[i][j] = 0ull;

    float4 a0 = *(const float4*)(arow + lk);
    float4 a1 = *(const float4*)(arow + lk + 4);
    float4 bv0 = *(const float4*)(brow + lk);
    float4 bv1 = *(const float4*)(brow + lk + 4);

    #pragma unroll 1
    for (int p = 0; p < 16; p++) {
        __syncthreads();
        As[lk+0][lr] = a0.x; As[lk+1][lr] = a0.y; As[lk+2][lr] = a0.z; As[lk+3][lr] = a0.w;
        As[lk+4][lr] = a1.x; As[lk+5][lr] = a1.y; As[lk+6][lr] = a1.z; As[lk+7][lr] = a1.w;
        Bs[lk+0][lr] = bv0.x; Bs[lk+1][lr] = bv0.y; Bs[lk+2][lr] = bv0.z; Bs[lk+3][lr] = bv0.w;
        Bs[lk+4][lr] = bv1.x; Bs[lk+5][lr] = bv1.y; Bs[lk+6][lr] = bv1.z; Bs[lk+7][lr] = bv1.w;
        __syncthreads();
        if (p < 15) {
            const int ko = (p + 1) * 16 + lk;
            a0  = *(const float4*)(arow + ko);
            a1  = *(const float4*)(arow + ko + 4);
            bv0 = *(const float4*)(brow + ko);
            bv1 = *(const float4*)(brow + ko + 4);
        }
        #pragma unroll
        for (int k = 0; k < 16; k++) {
            ulonglong2 ax = *(const ulonglong2*)(&As[k][tx * 8]);      // batch pairs (0,1),(2,3)
            ulonglong2 ay = *(const ulonglong2*)(&As[k][tx * 8 + 4]);  // batch pairs (4,5),(6,7)
            float4 bb0 = *(const float4*)(&Bs[k][ty * 8]);
            float4 bb1 = *(const float4*)(&Bs[k][ty * 8 + 4]);
            ull w0 = dup2(bb0.x), w1 = dup2(bb0.y), w2 = dup2(bb0.z), w3 = dup2(bb0.w);
            ull w4 = dup2(bb1.x), w5 = dup2(bb1.y), w6 = dup2(bb1.z), w7 = dup2(bb1.w);
            fma2(acc[0][0], ax.x, w0); fma2(acc[1][0], ax.y, w0);
            fma2(acc[2][0], ay.x, w0); fma2(acc[3][0], ay.y, w0);
            fma2(acc[0][1], ax.x, w1); fma2(acc[1][1], ax.y, w1);
            fma2(acc[2][1], ay.x, w1); fma2(acc[3][1], ay.y, w1);
            fma2(acc[0][2], ax.x, w2); fma2(acc[1][2], ax.y, w2);
            fma2(acc[2][2], ay.x, w2); fma2(acc[3][2], ay.y, w2);
            fma2(acc[0][3], ax.x, w3); fma2(acc[1][3], ax.y, w3);
            fma2(acc[2][3], ay.x, w3); fma2(acc[3][3], ay.y, w3);
            fma2(acc[0][4], ax.x, w4); fma2(acc[1][4], ax.y, w4);
            fma2(acc[2][4], ay.x, w4); fma2(acc[3][4], ay.y, w4);
            fma2(acc[0][5], ax.x, w5); fma2(acc[1][5], ax.y, w5);
            fma2(acc[2][5], ay.x, w5); fma2(acc[3][5], ay.y, w5);
            fma2(acc[0][6], ax.x, w6); fma2(acc[1][6], ax.y, w6);
            fma2(acc[2][6], ay.x, w6); fma2(acc[3][6], ay.y, w6);
            fma2(acc[0][7], ax.x, w7); fma2(acc[1][7], ax.y, w7);
            fma2(acc[2][7], ay.x, w7); fma2(acc[3][7], ay.y, w7);
        }
    }

    // coalesced transposed store: g_xp[((dir*SS+t)*G4 + n)*BB + b], batches tx*8..+8
    const size_t obase = ((size_t)dir * SS + t) * G4;
    #pragma unroll
    for (int j = 0; j < 8; j++) {
        const int n = n0 + ty * 8 + j;
        const float bs = bias[n];
        float r0, r1, r2, r3, r4, r5, r6, r7;
        upk2(acc[0][j], r0, r1); upk2(acc[1][j], r2, r3);
        upk2(acc[2][j], r4, r5); upk2(acc[3][j], r6, r7);
        float4 o0, o1;
        o0.x = r0 + bs; o0.y = r1 + bs; o0.z = r2 + bs; o0.w = r3 + bs;
        o1.x = r4 + bs; o1.y = r5 + bs; o1.z = r6 + bs; o1.w = r7 + bs;
        float* dst = g_xp + (obase + n) * BB + tx * 8;
        *(float4*)dst = o0;
        *(float4*)(dst + 4) = o1;
    }
}

// ---------------- persistent bidirectional LSTM recurrence ----------------
// 128 blocks: [0,64) fwd, [64,128) rev. Block owns 4 hidden dims = 16 gate cols.
// h staged via TMA bulk (2 halves, 2 mbarriers); FFMA2 GEMM, reg-duplicated W.
__global__ void __launch_bounds__(256, 1) lstm_kernel(const float* __restrict__ W_f,
                                                      const float* __restrict__ W_r)
{
    extern __shared__ float sm[];
    float* h_s = sm;                       // [k=256][b=128]  (128 KB)
    float* w_s = h_s + 256 * 128;          // [k=256][c=16]
    float* pg  = w_s + 256 * 16;           // [half=2][c=16][b=128]
    float* x_s = pg  + 2 * 16 * 128;       // [c=16][b=128]
    float* c_s = x_s + 16 * 128;           // [d=4][b=128]
    // mbarriers at end, 16B aligned
    const unsigned smem_base = (unsigned)__cvta_generic_to_shared(sm);
    const unsigned mbarA = smem_base + LSTM_SMEM_FLOATS * 4;
    const unsigned mbarB = mbarA + 8;

    const int tid = threadIdx.x;
    const int dir = blockIdx.x >> 6;
    const int blk = blockIdx.x & 63;
    const int d0  = blk * DPB;
    const float* W = dir ? W_r : W_f;

    if (tid == 0) { mbar_init(mbarA, 1); mbar_init(mbarB, 1); }

    // load W slice transposed: w_s[k][c] = W[q*256+d0+dd][k], c = q*4+dd
    {
        const int c  = tid >> 4;               // 0..15
        const int q  = c >> 2, dd = c & 3;
        const int grow = q * 256 + d0 + dd;
        const int kc = (tid & 15) * 16;
        const float* wp = W + (size_t)grow * 256 + kc;
        #pragma unroll
        for (int kk = 0; kk < 16; kk++)
            w_s[(kc + kk) * 16 + c] = wp[kk];
    }
    for (int i = tid; i < DPB * BB; i += 256) c_s[i] = 0.f;
    __syncthreads();

    const int half = tid >> 7;           // k range half*128 .. +128
    const int wt   = tid & 127;
    const int bg   = wt >> 2;            // 0..31 -> batches bg*4..+3
    const int cq   = wt & 3;             // 0..3  -> cols cq*4..+3 (gate cq, dims 0..3)
    const int b0   = bg * 4;

    const float* xpT       = g_xp   + (size_t)dir * SS * G4 * BB;
    float*       hout_base = g_hout + (size_t)dir * SS * HH * BB;
    const unsigned h_addr = (unsigned)__cvta_generic_to_shared(h_s);
    const unsigned x_addr = (unsigned)__cvta_generic_to_shared(x_s);

    for (int ti = 0; ti < SS; ti++) {
        const int t = dir ? (SS - 1 - ti) : ti;
        const int par = ti & 1;
        const float* hr = g_hcur + (dir * 2 + par) * (HH * BB);
        float*       hw = g_hcur + (dir * 2 + (par ^ 1)) * (HH * BB);

        // --- h staging via TMA bulk: 2 x 64KB, one mbarrier per half
        if (tid == 0) {
            mbar_expect(mbarA, 65536u);
            bulk_g2s(h_addr, hr, 65536u, mbarA);
            mbar_expect(mbarB, 65536u);
            bulk_g2s(h_addr + 65536u, (const char*)hr + 65536, 65536u, mbarB);
        }
        // xp slice via cp.async (half0 threads, 4 x 16B each = 8KB)
        if (half == 0) {
            const float* xt = xpT + (size_t)t * G4 * BB;
            #pragma unroll
            for (int i = 0; i < 4; i++) {
                int id = i * 128 + wt;             // 0..511 float4 units
                int c = id >> 5, bq = id & 31;
                int q = c >> 2, dd = c & 3;
                const float* s = xt + (size_t)(q * 256 + d0 + dd) * BB + bq * 4;
                cp16(x_addr + id * 16, s);
            }
            CP_COMMIT();
            mbar_wait(mbarA, par);
        } else {
            mbar_wait(mbarB, par);
        }

        // --- GEMM over this half's k range: 16 cells (4b x 4c), FFMA2 batch pairs
        ull a0[4], a1[4];   // a0[j] = (b0,b1) col j ; a1[j] = (b2,b3) col j
        #pragma unroll
        for (int j = 0; j < 4; j++) { a0[j] = 0ull; a1[j] = 0ull; }

        const float* hp = h_s + half * 128 * 128 + b0;
        const float* wp = w_s + half * 128 * 16 + cq * 4;
        #pragma unroll 8
        for (int k = 0; k < 128; k++) {
            ulonglong2 hv = *(const ulonglong2*)(hp + k * 128);
            float4 wv = *(const float4*)(wp + k * 16);
            ull w0 = dup2(wv.x), w1 = dup2(wv.y), w2 = dup2(wv.z), w3 = dup2(wv.w);
            fma2(a0[0], hv.x, w0); fma2(a1[0], hv.y, w0);
            fma2(a0[1], hv.x, w1); fma2(a1[1], hv.y, w1);
            fma2(a0[2], hv.x, w2); fma2(a1[2], hv.y, w2);
            fma2(a0[3], hv.x, w3); fma2(a1[3], hv.y, w3);
        }

        // write partials: pg[half][c][b]
        {
            float* pgh = pg + half * 2048;
            #pragma unroll
            for (int j = 0; j < 4; j++) {
                ulonglong2 s; s.x = a0[j]; s.y = a1[j];
                *(ulonglong2*)(pgh + (cq * 4 + j) * 128 + b0) = s;
            }
        }
        if (half == 0) asm volatile("cp.async.wait_group 0;");  // xp group done
        __syncthreads();

        // --- gate math: 512 (d,b) pairs, 2 per thread; keep hv for deferred hout store
        float hvv[2]; int dl[2], bl[2];
        #pragma unroll
        for (int r = 0; r < 2; r++) {
            const int idx = tid + r * 256;
            const int d = idx >> 7, b = idx & 127;
            const float gi = pg[(0*4+d)*128+b] + pg[2048+(0*4+d)*128+b] + x_s[(0*4+d)*128+b];
            const float gf = pg[(1*4+d)*128+b] + pg[2048+(1*4+d)*128+b] + x_s[(1*4+d)*128+b];
            const float gg = pg[(2*4+d)*128+b] + pg[2048+(2*4+d)*128+b] + x_s[(2*4+d)*128+b];
            const float go = pg[(3*4+d)*128+b] + pg[2048+(3*4+d)*128+b] + x_s[(3*4+d)*128+b];
            const float cp = c_s[d * 128 + b];
            const float si = 1.f / (1.f + expf(-gi));
            const float sf = 1.f / (1.f + expf(-gf));
            const float so = 1.f / (1.f + expf(-go));
            const float cn = sf * cp + si * tanhf(gg);
            const float hv = so * tanhf(cn);
            c_s[d * 128 + b] = cn;
            __stcg(hw + (d0 + d) * BB + b, hv);
            hvv[r] = hv; dl[r] = d; bl[r] = b;
        }

        // --- grid barrier: acq_rel arrive, coalesced hout stores overlapped with poll
        __syncthreads();   // all hw stores issued; cta-scope order feeds tid0's release
        int need_poll = 0;
        if (tid == 0) {
            const unsigned target = (unsigned)(NBLK * (ti + 1));
            unsigned a;
            asm volatile("atom.add.acq_rel.gpu.u32 %0, [%1], 1;"
                         : "=r"(a) : "l"(&g_bar_cnt[dir]) : "memory");
            if (a == target - 1) {
                asm volatile("st.release.gpu.u32 [%0], %1;"
                             :: "l"(&g_bar_flag[dir]), "r"((unsigned)(ti + 1)) : "memory");
            } else {
                need_poll = 1;
            }
        }
        // hout stores, coalesced layout [dir][t][d][b] (read only post-kernel)
        #pragma unroll
        for (int r = 0; r < 2; r++)
            hout_base[((size_t)t * HH + d0 + dl[r]) * BB + bl[r]] = hvv[r];
        if (need_poll) {
            unsigned f;
            do {
                asm volatile("ld.acquire.gpu.u32 %0, [%1];"
                             : "=r"(f) : "l"(&g_bar_flag[dir]) : "memory");
                if (f >= (unsigned)(ti + 1)) break;
                __nanosleep(32);
            } while (true);
        }
        __syncthreads();
    }
}

// ---------------- emissions: one block per t ----------------
// reads g_hout [dir][t][d][b] slabs; emis[b][t][tag] = sum_d h*w + bias
__global__ void __launch_bounds__(256, 2)
emis_kernel(const float* __restrict__ fcW, const float* __restrict__ fcb)
{
    extern __shared__ float esm[];
    float* wT   = esm;                 // [d 512][tag 20] transposed fc_W
    float* h_sh = wT + 512 * 20;       // [d 64][b 128] chunk
    float* b_sh = h_sh + 64 * 128;     // [20]

    const int tid = threadIdx.x;
    const int t = blockIdx.x;

    for (int i = tid; i < 512 * 20; i += 256) {
        int d = i / 20, tg = i - d * 20;
        wT[i] = fcW[tg * 512 + d];
    }
    if (tid < NT) b_sh[tid] = fcb[tid];

    const int b = tid >> 1;          // 0..127
    const int th = tid & 1;          // tags th*10..+9
    ull acc2[5] = {0ull, 0ull, 0ull, 0ull, 0ull};

    for (int dir = 0; dir < 2; dir++) {
        const float* hb = g_hout + ((size_t)dir * SS + t) * (HH * BB);
        for (int ch = 0; ch < 4; ch++) {
            __syncthreads();
            const float4* src = (const float4*)(hb + ch * 64 * 128);
            float4* dst = (float4*)h_sh;
            #pragma unroll
            for (int i = 0; i < 8; i++) dst[i * 256 + tid] = src[i * 256 + tid];
            __syncthreads();
            const float* wp = wT + (dir * 256 + ch * 64) * 20 + th * 10;
            #pragma unroll 8
            for (int d = 0; d < 64; d++) {
                ull hv = dup2(h_sh[d * 128 + b]);
                const float* w = wp + d * 20;
                fma2(acc2[0], hv, *(const ull*)(w));
                fma2(acc2[1], hv, *(const ull*)(w + 2));
                fma2(acc2[2], hv, *(const ull*)(w + 4));
                fma2(acc2[3], hv, *(const ull*)(w + 6));
                fma2(acc2[4], hv, *(const ull*)(w + 8));
            }
        }
    }

    float* o = g_emis + ((size_t)b * SS + t) * NT + th * 10;
    #pragma unroll
    for (int j = 0; j < 5; j++) {
        float lo, hi; upk2(acc2[j], lo, hi);
        o[2*j]   = lo + b_sh[th * 10 + 2*j];
        o[2*j+1] = hi + b_sh[th * 10 + 2*j + 1];
    }
}

// ---------------- Viterbi: one block (1 warp) per batch item ----------------
__global__ void viterbi_kernel(const int* __restrict__ xs,
                               const float* __restrict__ trans,
                               const float* __restrict__ start_t,
                               const float* __restrict__ end_t,
                               float* __restrict__ out,
                               int write_scores, int write_tags, int tag_off)
{
    __shared__ float tr[NT * NT];
    __shared__ float sc[NT];
    __shared__ unsigned char bp[SS * NT];

    const int b = blockIdx.x, tid = threadIdx.x;
    for (int i = tid; i < NT * NT; i += 32) tr[i] = trans[i];
    if (tid < NT) sc[tid] = start_t[tid] + g_emis[(size_t)b * SS * NT + tid];
    __syncwarp();

    for (int s = 1; s < SS; s++) {
        float ns = 0.f; int nb = 0;
        if (tid < NT) {
            float best = -1e30f; int bi = 0;
            #pragma unroll
            for (int i = 0; i < NT; i++) {
                float v = sc[i] + tr[i * NT + tid];
                if (v > best) { best = v; bi = i; }   // first-max on ties
            }
            const int m = xs[b * SS + s] > 0;
            const float em = g_emis[((size_t)b * SS + s) * NT + tid];
            ns = m ? (best + em) : sc[tid];
            nb = m ? bi : tid;
        }
        __syncwarp();
        if (tid < NT) { sc[tid] = ns; bp[s * NT + tid] = (unsigned char)nb; }
        __syncwarp();
    }

    if (tid == 0) {
        float best = -1e30f; int bi = 0;
        for (int j = 0; j < NT; j++) {
            float v = sc[j] + end_t[j];
            if (v > best) { best = v; bi = j; }
        }
        if (write_scores) out[b] = best;
        if (write_tags) {
            int tag = bi;
            out[tag_off + b * SS + (SS - 1)] = (float)tag;
            for (int s = SS - 2; s >= 0; s--) {
                tag = bp[(s + 1) * NT + tag];
                out[tag_off + b * SS + s] = (float)tag;
            }
        }
    }
}

// ---------------- launch ----------------
extern "C" void kernel_launch(void* const* d_in, const int* in_sizes, int n_in,
                              void* d_out, int out_size)
{
    const int*   xs      = (const int*)  d_in[0];
    const float* emb     = (const float*)d_in[1];
    const float* W_ih_f  = (const float*)d_in[2];
    const float* W_hh_f  = (const float*)d_in[3];
    const float* b_f     = (const float*)d_in[4];
    const float* W_ih_r  = (const float*)d_in[5];
    const float* W_hh_r  = (const float*)d_in[6];
    const float* b_r     = (const float*)d_in[7];
    const float* fc_W    = (const float*)d_in[8];
    const float* fc_b    = (const float*)d_in[9];
    const float* trans   = (const float*)d_in[10];
    const float* start_t = (const float*)d_in[11];
    const float* end_t   = (const float*)d_in[12];
    float* out = (float*)d_out;

    cudaFuncSetAttribute(lstm_kernel, cudaFuncAttributeMaxDynamicSharedMemorySize, LSTM_SMEM);
    cudaFuncSetAttribute(emis_kernel, cudaFuncAttributeMaxDynamicSharedMemorySize, EMIS_SMEM);

    init_kernel<<<256, 256>>>();

    // grid: x = t, y = n-tile (128 wide), z = dir
    dim3 gA(SS, G4 / 128, 2);
    input_proj_kernel<<<gA, 256>>>(xs, emb, W_ih_f, b_f, W_ih_r, b_r);

    lstm_kernel<<<2 * NBLK, 256, LSTM_SMEM>>>(W_hh_f, W_hh_r);

    emis_kernel<<<SS, 256, EMIS_SMEM>>>(fc_W, fc_b);

    int ws = 0, wt = 0, toff = 0;
    if (out_size >= BB + BB * SS)      { ws = 1; wt = 1; toff = BB; }
    else if (out_size >= BB * SS)      { ws = 0; wt = 1; toff = 0; }
    else                               { ws = 1; wt = 0; toff = 0; }
    viterbi_kernel<<<BB, 32>>>(xs, trans, start_t, end_t, out, ws, wt, toff);
}